// round 5
// baseline (speedup 1.0000x reference)
#include <cuda_runtime.h>
#include <math.h>

#define BANDS 64
#define CHA   64
#define NPIX  16384
#define RRANK 3
#define ITEN  20

#define PB_CTAS 32          // CTAs per band for passB / gram
#define SUBT    4           // subtiles per CTA
#define TP      128         // pixels per subtile
#define PIX_PER_CTA (SUBT*TP)   // 512
#define NTHREADS 256
#define MAXSWEEP 10

// ---- device scratch (static module memory; no runtime allocation) ----
__device__ float  g_L[(size_t)BANDS*CHA*NPIX];                 // 256 MB
__device__ float  g_Gpart[(size_t)BANDS*PB_CTAS*CHA*CHA];     // 33.5 MB
__device__ float  g_Ur[BANDS*CHA*RRANK];
__device__ float  g_c[(size_t)BANDS*RRANK*NPIX];              // 12.6 MB
__device__ float  g_losspart[2][ITEN][BANDS*PB_CTAS];
__device__ double g_dpart[1024];
__device__ float  g_rho0;

// ============================================================
// rho0 = 0.5 * mean(W)  (deterministic, double accumulation)
// ============================================================
__global__ __launch_bounds__(NTHREADS) void k_wsum1(const float* __restrict__ W)
{
    __shared__ double rd[NTHREADS];
    const size_t base = (size_t)blockIdx.x * 65536;
    double s = 0.0;
    for (int i = threadIdx.x; i < 65536; i += NTHREADS) s += (double)W[base + i];
    rd[threadIdx.x] = s;
    __syncthreads();
    for (int st = NTHREADS/2; st > 0; st >>= 1) {
        if (threadIdx.x < st) rd[threadIdx.x] += rd[threadIdx.x + st];
        __syncthreads();
    }
    if (threadIdx.x == 0) g_dpart[blockIdx.x] = rd[0];
}

__global__ __launch_bounds__(NTHREADS) void k_wsum2()
{
    __shared__ double rd[NTHREADS];
    double s = 0.0;
    for (int i = threadIdx.x; i < 1024; i += NTHREADS) s += g_dpart[i];
    rd[threadIdx.x] = s;
    __syncthreads();
    for (int st = NTHREADS/2; st > 0; st >>= 1) {
        if (threadIdx.x < st) rd[threadIdx.x] += rd[threadIdx.x + st];
        __syncthreads();
    }
    if (threadIdx.x == 0) g_rho0 = (float)(0.5 * rd[0] / 67108864.0);
}

// ============================================================
// Gram of initial L (= x):  partial G per CTA, deterministic
// ============================================================
__global__ __launch_bounds__(NTHREADS) void k_gram0(const float* __restrict__ x)
{
    __shared__ float tile[TP][CHA + 1];
    const int tid = threadIdx.x;
    const int cta = blockIdx.x;
    const int b   = blockIdx.y;

    float accG[16];
#pragma unroll
    for (int i = 0; i < 16; ++i) accG[i] = 0.0f;

    const int tr = (tid >> 4) << 2;
    const int tc = (tid & 15) << 2;

    for (int s = 0; s < SUBT; ++s) {
        const int pix0 = cta * PIX_PER_CTA + s * TP;
#pragma unroll 4
        for (int k = 0; k < 32; ++k) {
            int lin = k * NTHREADS + tid;
            int c   = lin >> 7;
            int p2  = lin & 127;
            tile[p2][c] = x[(((size_t)b * CHA + c) << 14) + pix0 + p2];
        }
        __syncthreads();
#pragma unroll 4
        for (int p = 0; p < TP; ++p) {
            float a0 = tile[p][tr], a1 = tile[p][tr+1], a2 = tile[p][tr+2], a3 = tile[p][tr+3];
            float b0 = tile[p][tc], b1 = tile[p][tc+1], b2 = tile[p][tc+2], b3 = tile[p][tc+3];
            accG[0]  += a0*b0; accG[1]  += a0*b1; accG[2]  += a0*b2; accG[3]  += a0*b3;
            accG[4]  += a1*b0; accG[5]  += a1*b1; accG[6]  += a1*b2; accG[7]  += a1*b3;
            accG[8]  += a2*b0; accG[9]  += a2*b1; accG[10] += a2*b2; accG[11] += a2*b3;
            accG[12] += a3*b0; accG[13] += a3*b1; accG[14] += a3*b2; accG[15] += a3*b3;
        }
        __syncthreads();
    }
    const size_t gb = ((size_t)(b * PB_CTAS + cta)) * (CHA * CHA);
#pragma unroll
    for (int i = 0; i < 4; ++i)
#pragma unroll
        for (int j = 0; j < 4; ++j)
            g_Gpart[gb + (size_t)(tr + i) * CHA + (tc + j)] = accG[i * 4 + j];
}

// ============================================================
// Eigen kernel: reduce G partials, parallel Jacobi, write Ur
// ============================================================
__device__ __forceinline__ int rrperm(int k, int r)
{
    return (k == 0) ? 0 : 1 + ((k - 1 + r) % 63);
}

__global__ __launch_bounds__(NTHREADS) void k_eigen()
{
    __shared__ float As[64 * 65];
    __shared__ float Vs[64 * 65];
    __shared__ float cs_c[32], cs_s[32];
    __shared__ int   ppv[32], qqv[32];
    __shared__ float red[NTHREADS];
    __shared__ float soff, sdg;
    __shared__ int   sflag;
    __shared__ int   topi[RRANK];

    const int tid = threadIdx.x;
    const int b   = blockIdx.x;

    // reduce partial Grams (fixed order)
    for (int e = tid; e < CHA * CHA; e += NTHREADS) {
        float s = 0.0f;
        const size_t base = ((size_t)b * PB_CTAS) * (CHA * CHA) + e;
        for (int p = 0; p < PB_CTAS; ++p)
            s += g_Gpart[base + (size_t)p * (CHA * CHA)];
        As[(e >> 6) * 65 + (e & 63)] = s;
    }
    // V = I
    for (int e = tid; e < CHA * CHA; e += NTHREADS) {
        int rr = e >> 6, cc = e & 63;
        Vs[rr * 65 + cc] = (rr == cc) ? 1.0f : 0.0f;
    }
    __syncthreads();

    for (int sw = 0; sw < MAXSWEEP; ++sw) {
        for (int r = 0; r < 63; ++r) {
            if (tid < 32) {
                int a  = rrperm(tid, r);
                int b2 = rrperm(63 - tid, r);
                int p = a < b2 ? a : b2;
                int q = a < b2 ? b2 : a;
                ppv[tid] = p; qqv[tid] = q;
                float apq = As[p * 65 + q];
                float cc = 1.0f, ss = 0.0f;
                if (fabsf(apq) > 1e-30f) {
                    float tau = (As[q * 65 + q] - As[p * 65 + p]) / (2.0f * apq);
                    float tt  = 1.0f / (fabsf(tau) + sqrtf(1.0f + tau * tau));
                    if (tau < 0.0f) tt = -tt;
                    cc = 1.0f / sqrtf(1.0f + tt * tt);
                    ss = tt * cc;
                }
                cs_c[tid] = cc; cs_s[tid] = ss;
            }
            __syncthreads();
            // column updates on A and V  (B = A*J, V = V*J)
            for (int task = tid; task < 4096; task += NTHREADS) {
                int pi  = task >> 7;
                int rem = task & 127;
                int row = rem & 63;
                int p = ppv[pi], q = qqv[pi];
                float c = cs_c[pi], s = cs_s[pi];
                if (rem < 64) {
                    float ap = As[row * 65 + p], aq = As[row * 65 + q];
                    As[row * 65 + p] = c * ap - s * aq;
                    As[row * 65 + q] = s * ap + c * aq;
                } else {
                    float vp = Vs[row * 65 + p], vq = Vs[row * 65 + q];
                    Vs[row * 65 + p] = c * vp - s * vq;
                    Vs[row * 65 + q] = s * vp + c * vq;
                }
            }
            __syncthreads();
            // row updates on A  (A = J^T * B)
            for (int task = tid; task < 2048; task += NTHREADS) {
                int pi  = task >> 6;
                int col = task & 63;
                int p = ppv[pi], q = qqv[pi];
                float c = cs_c[pi], s = cs_s[pi];
                float ap = As[p * 65 + col], aq = As[q * 65 + col];
                As[p * 65 + col] = c * ap - s * aq;
                As[q * 65 + col] = s * ap + c * aq;
            }
            __syncthreads();
        }
        // convergence check (deterministic, uniform branch)
        float off = 0.0f, dg = 0.0f;
        for (int e = tid; e < 4096; e += NTHREADS) {
            int rr = e >> 6, cc = e & 63;
            float v = As[rr * 65 + cc];
            if (rr == cc) dg += v * v; else off += v * v;
        }
        red[tid] = off; __syncthreads();
        for (int st = NTHREADS/2; st > 0; st >>= 1) {
            if (tid < st) red[tid] += red[tid + st];
            __syncthreads();
        }
        if (tid == 0) soff = red[0];
        __syncthreads();
        red[tid] = dg; __syncthreads();
        for (int st = NTHREADS/2; st > 0; st >>= 1) {
            if (tid < st) red[tid] += red[tid + st];
            __syncthreads();
        }
        if (tid == 0) { sdg = red[0]; sflag = (soff < 1e-11f * sdg) ? 1 : 0; }
        __syncthreads();
        if (sflag) break;
    }

    // pick top-3 eigenvalues (descending), indices into V columns
    if (tid == 0) {
        int t0 = -1, t1 = -1, t2 = -1;
        for (int j = 0; j < RRANK; ++j) {
            float best = -3.4e38f; int bi = -1;
            for (int c = 0; c < 64; ++c) {
                if (c == t0 || c == t1 || c == t2) continue;
                float v = As[c * 65 + c];
                if (v > best) { best = v; bi = c; }
            }
            if (j == 0) t0 = bi; else if (j == 1) t1 = bi; else t2 = bi;
            topi[j] = bi;
        }
    }
    __syncthreads();
    if (tid < CHA * RRANK) {
        int c = tid / RRANK, j = tid % RRANK;
        g_Ur[b * (CHA * RRANK) + tid] = Vs[c * 65 + topi[j]];
    }
}

// ============================================================
// passU:  c = Ur^T L   (3 x NPIX per band)
// ============================================================
__global__ __launch_bounds__(NTHREADS) void k_passU(const float* __restrict__ x, int useX)
{
    __shared__ float ur[CHA * RRANK];
    const int b = blockIdx.y;
    const int n = blockIdx.x * NTHREADS + threadIdx.x;
    if (threadIdx.x < CHA * RRANK) ur[threadIdx.x] = g_Ur[b * (CHA * RRANK) + threadIdx.x];
    __syncthreads();

    const float* __restrict__ Ls = useX ? x : (const float*)g_L;
    const size_t base = ((size_t)b * CHA) << 14;
    float a0 = 0.0f, a1 = 0.0f, a2 = 0.0f;
#pragma unroll 8
    for (int c = 0; c < CHA; ++c) {
        float l = Ls[base + ((size_t)c << 14) + n];
        a0 += ur[c * 3 + 0] * l;
        a1 += ur[c * 3 + 1] * l;
        a2 += ur[c * 3 + 2] * l;
    }
    const size_t cb = ((size_t)b * RRANK) << 14;
    g_c[cb + n]            = a0;
    g_c[cb + NPIX + n]     = a1;
    g_c[cb + 2 * NPIX + n] = a2;
}

// ============================================================
// passB: UV, losses, L_{t+1}, fused Gram of L_{t+1}
//        (final iter: write UV to out, skip L/Gram)
// ============================================================
__global__ __launch_bounds__(NTHREADS) void k_passB(const float* __restrict__ x,
                                                    const float* __restrict__ W,
                                                    float* __restrict__ out,
                                                    int t, int final)
{
    __shared__ float tile[TP][CHA + 1];
    __shared__ float ur[CHA * RRANK];
    __shared__ float red[NTHREADS];

    const int tid = threadIdx.x;
    const int cta = blockIdx.x;
    const int b   = blockIdx.y;

    if (tid < CHA * RRANK) ur[tid] = g_Ur[b * (CHA * RRANK) + tid];
    __syncthreads();

    const float rho = g_rho0 * powf(1.05f, (float)t);
    const int p   = tid & 127;
    const int h   = tid >> 7;
    const int ch0 = h * 32;
    const int tr  = (tid >> 4) << 2;
    const int tc  = (tid & 15) << 2;

    float accG[16];
#pragma unroll
    for (int i = 0; i < 16; ++i) accG[i] = 0.0f;
    float lF = 0.0f, lU = 0.0f;

    for (int s = 0; s < SUBT; ++s) {
        const int n = cta * PIX_PER_CTA + s * TP + p;
        const size_t cb = ((size_t)b * RRANK) << 14;
        const float c0 = g_c[cb + n];
        const float c1 = g_c[cb + NPIX + n];
        const float c2 = g_c[cb + 2 * NPIX + n];
        const size_t base = (((size_t)b * CHA + ch0) << 14) + n;

#pragma unroll 8
        for (int k = 0; k < 32; ++k) {
            const int cc = ch0 + k;
            const size_t idx = base + ((size_t)k << 14);
            float uv = ur[cc * 3] * c0 + ur[cc * 3 + 1] * c1 + ur[cc * 3 + 2] * c2;
            float xv = x[idx];
            float wv = W[idx];
            float d  = uv - xv;
            lF += wv * d * d;
            lU += uv * uv;
            if (final) {
                out[idx] = uv;
            } else {
                float mu = rho / (wv + rho);
                float ln = (1.0f - mu) * xv + mu * uv;
                g_L[idx]    = ln;
                tile[p][cc] = ln;
            }
        }
        if (!final) {
            __syncthreads();
#pragma unroll 4
            for (int pp = 0; pp < TP; ++pp) {
                float a0 = tile[pp][tr], a1 = tile[pp][tr+1], a2 = tile[pp][tr+2], a3 = tile[pp][tr+3];
                float b0 = tile[pp][tc], b1 = tile[pp][tc+1], b2 = tile[pp][tc+2], b3 = tile[pp][tc+3];
                accG[0]  += a0*b0; accG[1]  += a0*b1; accG[2]  += a0*b2; accG[3]  += a0*b3;
                accG[4]  += a1*b0; accG[5]  += a1*b1; accG[6]  += a1*b2; accG[7]  += a1*b3;
                accG[8]  += a2*b0; accG[9]  += a2*b1; accG[10] += a2*b2; accG[11] += a2*b3;
                accG[12] += a3*b0; accG[13] += a3*b1; accG[14] += a3*b2; accG[15] += a3*b3;
            }
            __syncthreads();
        }
    }

    if (!final) {
        const size_t gb = ((size_t)(b * PB_CTAS + cta)) * (CHA * CHA);
#pragma unroll
        for (int i = 0; i < 4; ++i)
#pragma unroll
            for (int j = 0; j < 4; ++j)
                g_Gpart[gb + (size_t)(tr + i) * CHA + (tc + j)] = accG[i * 4 + j];
    }

    // deterministic loss partials
    red[tid] = lF; __syncthreads();
    for (int st = NTHREADS/2; st > 0; st >>= 1) {
        if (tid < st) red[tid] += red[tid + st];
        __syncthreads();
    }
    if (tid == 0) g_losspart[0][t][b * PB_CTAS + cta] = red[0];
    __syncthreads();
    red[tid] = lU; __syncthreads();
    for (int st = NTHREADS/2; st > 0; st >>= 1) {
        if (tid < st) red[tid] += red[tid + st];
        __syncthreads();
    }
    if (tid == 0) g_losspart[1][t][b * PB_CTAS + cta] = red[0];
}

// ============================================================
// final loss reduction -> out tail
// ============================================================
__global__ __launch_bounds__(NTHREADS) void k_loss_final(float* __restrict__ out)
{
    __shared__ double rd[NTHREADS];
    const int id   = blockIdx.x;       // 0..39
    const int type = id / ITEN;        // 0 = loss_F, 1 = loss
    const int t    = id % ITEN;
    double s = 0.0;
    for (int i = threadIdx.x; i < BANDS * PB_CTAS; i += NTHREADS)
        s += (double)g_losspart[type][t][i];
    rd[threadIdx.x] = s;
    __syncthreads();
    for (int st = NTHREADS/2; st > 0; st >>= 1) {
        if (threadIdx.x < st) rd[threadIdx.x] += rd[threadIdx.x + st];
        __syncthreads();
    }
    if (threadIdx.x == 0)
        out[(size_t)67108864 + (size_t)type * ITEN + t] = (float)(rd[0] / 67108864.0);
}

// ============================================================
extern "C" void kernel_launch(void* const* d_in, const int* in_sizes, int n_in,
                              void* d_out, int out_size)
{
    const float* x = (const float*)d_in[0];
    const float* W = (const float*)d_in[1];
    float* out = (float*)d_out;

    k_wsum1<<<1024, NTHREADS>>>(W);
    k_wsum2<<<1, NTHREADS>>>();
    k_gram0<<<dim3(PB_CTAS, BANDS), NTHREADS>>>(x);

    for (int t = 0; t < ITEN; ++t) {
        k_eigen<<<BANDS, NTHREADS>>>();
        k_passU<<<dim3(NPIX / NTHREADS, BANDS), NTHREADS>>>(x, t == 0 ? 1 : 0);
        k_passB<<<dim3(PB_CTAS, BANDS), NTHREADS>>>(x, W, out, t, (t == ITEN - 1) ? 1 : 0);
    }
    k_loss_final<<<40, NTHREADS>>>(out);
}

// round 6
// speedup vs baseline: 2.1953x; 2.1953x over previous
#include <cuda_runtime.h>
#include <math.h>

#define BANDS 64
#define CHA   64
#define NPIX  16384
#define RRANK 3
#define ITEN  20

#define PB_CTAS 32          // CTAs per band
#define SUBT    4           // subtiles per CTA
#define TP      128         // pixels per subtile
#define PIX_PER_CTA (SUBT*TP)   // 512
#define NTHREADS 256
#define MAXSWEEP 10
#define TSTR 68             // tile row stride in floats (272B, 16B-aligned)

// ---- device scratch (static module memory; no runtime allocation) ----
__device__ float  g_L[(size_t)BANDS*CHA*NPIX];                 // 256 MB
__device__ float  g_Gpart[(size_t)BANDS*PB_CTAS*CHA*CHA];      // 33.5 MB
__device__ float  g_Ur[BANDS*CHA*RRANK];
__device__ float  g_V[(size_t)BANDS*CHA*CHA];                  // 1 MB (warm-start V)
__device__ float  g_T[(size_t)BANDS*CHA*CHA];                  // 1 MB (matmul temp)
__device__ float  g_losspart[2][ITEN][BANDS*PB_CTAS];
__device__ double g_dpart[1024];
__device__ float  g_rho0;

// packed f32x2 fused-multiply-add (sm_100+ PTX; ptxas never auto-fuses)
#define FMA2(acc,aa,bb) asm("fma.rn.f32x2 %0, %1, %2, %3;" : "=l"(acc) : "l"(aa), "l"(bb), "l"(acc))
#define PACK2(dst,lo,hi) asm("mov.b64 %0,{%1,%2};" : "=l"(dst) : "f"(lo), "f"(hi))
#define PACKD(dst,v)     asm("mov.b64 %0,{%1,%1};" : "=l"(dst) : "f"(v))
#define UNPK2(lo,hi,src) asm("mov.b64 {%0,%1}, %2;" : "=f"(lo), "=f"(hi) : "l"(src))

// ============================================================
// rho0 = 0.5 * mean(W)  (deterministic, double accumulation)
// ============================================================
__global__ __launch_bounds__(NTHREADS) void k_wsum1(const float* __restrict__ W)
{
    __shared__ double rd[NTHREADS];
    const size_t base = (size_t)blockIdx.x * 65536;
    double s = 0.0;
    for (int i = threadIdx.x; i < 65536; i += NTHREADS) s += (double)W[base + i];
    rd[threadIdx.x] = s;
    __syncthreads();
    for (int st = NTHREADS/2; st > 0; st >>= 1) {
        if (threadIdx.x < st) rd[threadIdx.x] += rd[threadIdx.x + st];
        __syncthreads();
    }
    if (threadIdx.x == 0) g_dpart[blockIdx.x] = rd[0];
}

__global__ __launch_bounds__(NTHREADS) void k_wsum2()
{
    __shared__ double rd[NTHREADS];
    double s = 0.0;
    for (int i = threadIdx.x; i < 1024; i += NTHREADS) s += g_dpart[i];
    rd[threadIdx.x] = s;
    __syncthreads();
    for (int st = NTHREADS/2; st > 0; st >>= 1) {
        if (threadIdx.x < st) rd[threadIdx.x] += rd[threadIdx.x + st];
        __syncthreads();
    }
    if (threadIdx.x == 0) g_rho0 = (float)(0.5 * rd[0] / 67108864.0);
}

// ============================================================
// init V = I per band (warm-start seed)
// ============================================================
__global__ __launch_bounds__(NTHREADS) void k_initV()
{
    const int b = blockIdx.x;
    for (int e = threadIdx.x; e < CHA * CHA; e += NTHREADS)
        g_V[(size_t)b * (CHA * CHA) + e] = ((e >> 6) == (e & 63)) ? 1.0f : 0.0f;
}

// ============================================================
// Gram of initial L (= x):  partial G per CTA, deterministic
// ============================================================
__global__ __launch_bounds__(NTHREADS) void k_gram0(const float* __restrict__ x)
{
    __shared__ float tile[TP][CHA + 1];
    const int tid = threadIdx.x;
    const int cta = blockIdx.x;
    const int b   = blockIdx.y;

    float accG[16];
#pragma unroll
    for (int i = 0; i < 16; ++i) accG[i] = 0.0f;

    const int tr = (tid >> 4) << 2;
    const int tc = (tid & 15) << 2;

    for (int s = 0; s < SUBT; ++s) {
        const int pix0 = cta * PIX_PER_CTA + s * TP;
#pragma unroll 4
        for (int k = 0; k < 32; ++k) {
            int lin = k * NTHREADS + tid;
            int c   = lin >> 7;
            int p2  = lin & 127;
            tile[p2][c] = x[(((size_t)b * CHA + c) << 14) + pix0 + p2];
        }
        __syncthreads();
#pragma unroll 4
        for (int p = 0; p < TP; ++p) {
            float a0 = tile[p][tr], a1 = tile[p][tr+1], a2 = tile[p][tr+2], a3 = tile[p][tr+3];
            float b0 = tile[p][tc], b1 = tile[p][tc+1], b2 = tile[p][tc+2], b3 = tile[p][tc+3];
            accG[0]  += a0*b0; accG[1]  += a0*b1; accG[2]  += a0*b2; accG[3]  += a0*b3;
            accG[4]  += a1*b0; accG[5]  += a1*b1; accG[6]  += a1*b2; accG[7]  += a1*b3;
            accG[8]  += a2*b0; accG[9]  += a2*b1; accG[10] += a2*b2; accG[11] += a2*b3;
            accG[12] += a3*b0; accG[13] += a3*b1; accG[14] += a3*b2; accG[15] += a3*b3;
        }
        __syncthreads();
    }
    const size_t gb = ((size_t)(b * PB_CTAS + cta)) * (CHA * CHA);
#pragma unroll
    for (int i = 0; i < 4; ++i)
#pragma unroll
        for (int j = 0; j < 4; ++j)
            g_Gpart[gb + (size_t)(tr + i) * CHA + (tc + j)] = accG[i * 4 + j];
}

// ============================================================
// Eigen kernel: reduce G partials, warm-start pre-rotation,
// parallel Jacobi with early convergence, write Ur + V
// ============================================================
__device__ __forceinline__ int rrperm(int k, int r)
{
    return (k == 0) ? 0 : 1 + ((k - 1 + r) % 63);
}

__global__ __launch_bounds__(NTHREADS) void k_eigen(int t)
{
    __shared__ float As[64 * 65];
    __shared__ float Vs[64 * 65];
    __shared__ float cs_c[32], cs_s[32];
    __shared__ int   ppv[32], qqv[32];
    __shared__ float red[NTHREADS];
    __shared__ float soff, sdg;
    __shared__ int   sflag;
    __shared__ int   topi[RRANK];

    const int tid = threadIdx.x;
    const int b   = blockIdx.x;
    const int tr  = (tid >> 4) << 2;
    const int tc  = (tid & 15) << 2;

    // reduce partial Grams (fixed order)
    for (int e = tid; e < CHA * CHA; e += NTHREADS) {
        float s = 0.0f;
        const size_t base = ((size_t)b * PB_CTAS) * (CHA * CHA) + e;
        for (int p = 0; p < PB_CTAS; ++p)
            s += g_Gpart[base + (size_t)p * (CHA * CHA)];
        As[(e >> 6) * 65 + (e & 63)] = s;
    }
    // load previous V (identity at t=0)
    for (int e = tid; e < CHA * CHA; e += NTHREADS)
        Vs[(e >> 6) * 65 + (e & 63)] = g_V[(size_t)b * (CHA * CHA) + e];
    __syncthreads();

    // warm-start pre-rotation: A <- V^T A V  (temp via global scratch)
    if (t > 0) {
        float* gT = g_T + (size_t)b * (CHA * CHA);
        float tt[16];
#pragma unroll
        for (int i = 0; i < 16; ++i) tt[i] = 0.0f;
        for (int k = 0; k < 64; ++k) {
            float a0 = As[(tr  ) * 65 + k], a1 = As[(tr+1) * 65 + k];
            float a2 = As[(tr+2) * 65 + k], a3 = As[(tr+3) * 65 + k];
            float v0 = Vs[k * 65 + tc], v1 = Vs[k * 65 + tc + 1];
            float v2 = Vs[k * 65 + tc + 2], v3 = Vs[k * 65 + tc + 3];
            tt[0]  += a0*v0; tt[1]  += a0*v1; tt[2]  += a0*v2; tt[3]  += a0*v3;
            tt[4]  += a1*v0; tt[5]  += a1*v1; tt[6]  += a1*v2; tt[7]  += a1*v3;
            tt[8]  += a2*v0; tt[9]  += a2*v1; tt[10] += a2*v2; tt[11] += a2*v3;
            tt[12] += a3*v0; tt[13] += a3*v1; tt[14] += a3*v2; tt[15] += a3*v3;
        }
#pragma unroll
        for (int i = 0; i < 4; ++i)
#pragma unroll
            for (int j = 0; j < 4; ++j)
                gT[(tr + i) * 64 + tc + j] = tt[i * 4 + j];
        __syncthreads();
#pragma unroll
        for (int i = 0; i < 16; ++i) tt[i] = 0.0f;
        for (int k = 0; k < 64; ++k) {
            float a0 = Vs[k * 65 + tr], a1 = Vs[k * 65 + tr + 1];
            float a2 = Vs[k * 65 + tr + 2], a3 = Vs[k * 65 + tr + 3];
            float v0 = gT[k * 64 + tc], v1 = gT[k * 64 + tc + 1];
            float v2 = gT[k * 64 + tc + 2], v3 = gT[k * 64 + tc + 3];
            tt[0]  += a0*v0; tt[1]  += a0*v1; tt[2]  += a0*v2; tt[3]  += a0*v3;
            tt[4]  += a1*v0; tt[5]  += a1*v1; tt[6]  += a1*v2; tt[7]  += a1*v3;
            tt[8]  += a2*v0; tt[9]  += a2*v1; tt[10] += a2*v2; tt[11] += a2*v3;
            tt[12] += a3*v0; tt[13] += a3*v1; tt[14] += a3*v2; tt[15] += a3*v3;
        }
        __syncthreads();
#pragma unroll
        for (int i = 0; i < 4; ++i)
#pragma unroll
            for (int j = 0; j < 4; ++j)
                As[(tr + i) * 65 + tc + j] = tt[i * 4 + j];
        __syncthreads();
    }

    for (int sw = 0; sw < MAXSWEEP; ++sw) {
        // convergence check BEFORE the sweep (warm starts exit immediately)
        float off = 0.0f, dg = 0.0f;
        for (int e = tid; e < 4096; e += NTHREADS) {
            int rr = e >> 6, cc = e & 63;
            float v = As[rr * 65 + cc];
            if (rr == cc) dg += v * v; else off += v * v;
        }
        red[tid] = off; __syncthreads();
        for (int st = NTHREADS/2; st > 0; st >>= 1) {
            if (tid < st) red[tid] += red[tid + st];
            __syncthreads();
        }
        if (tid == 0) soff = red[0];
        __syncthreads();
        red[tid] = dg; __syncthreads();
        for (int st = NTHREADS/2; st > 0; st >>= 1) {
            if (tid < st) red[tid] += red[tid + st];
            __syncthreads();
        }
        if (tid == 0) { sdg = red[0]; sflag = (soff < 1e-11f * sdg) ? 1 : 0; }
        __syncthreads();
        if (sflag) break;

        for (int r = 0; r < 63; ++r) {
            if (tid < 32) {
                int a  = rrperm(tid, r);
                int b2 = rrperm(63 - tid, r);
                int p = a < b2 ? a : b2;
                int q = a < b2 ? b2 : a;
                ppv[tid] = p; qqv[tid] = q;
                float apq = As[p * 65 + q];
                float cc = 1.0f, ss = 0.0f;
                if (fabsf(apq) > 1e-30f) {
                    float tau = (As[q * 65 + q] - As[p * 65 + p]) / (2.0f * apq);
                    float tt  = 1.0f / (fabsf(tau) + sqrtf(1.0f + tau * tau));
                    if (tau < 0.0f) tt = -tt;
                    cc = 1.0f / sqrtf(1.0f + tt * tt);
                    ss = tt * cc;
                }
                cs_c[tid] = cc; cs_s[tid] = ss;
            }
            __syncthreads();
            // column updates on A and V  (B = A*J, V = V*J)
            for (int task = tid; task < 4096; task += NTHREADS) {
                int pi  = task >> 7;
                int rem = task & 127;
                int row = rem & 63;
                int p = ppv[pi], q = qqv[pi];
                float c = cs_c[pi], s = cs_s[pi];
                if (rem < 64) {
                    float ap = As[row * 65 + p], aq = As[row * 65 + q];
                    As[row * 65 + p] = c * ap - s * aq;
                    As[row * 65 + q] = s * ap + c * aq;
                } else {
                    float vp = Vs[row * 65 + p], vq = Vs[row * 65 + q];
                    Vs[row * 65 + p] = c * vp - s * vq;
                    Vs[row * 65 + q] = s * vp + c * vq;
                }
            }
            __syncthreads();
            // row updates on A  (A = J^T * B)
            for (int task = tid; task < 2048; task += NTHREADS) {
                int pi  = task >> 6;
                int col = task & 63;
                int p = ppv[pi], q = qqv[pi];
                float c = cs_c[pi], s = cs_s[pi];
                float ap = As[p * 65 + col], aq = As[q * 65 + col];
                As[p * 65 + col] = c * ap - s * aq;
                As[q * 65 + col] = s * ap + c * aq;
            }
            __syncthreads();
        }
    }

    // pick top-3 eigenvalues (descending)
    if (tid == 0) {
        int t0 = -1, t1 = -1, t2 = -1;
        for (int j = 0; j < RRANK; ++j) {
            float best = -3.4e38f; int bi = -1;
            for (int c = 0; c < 64; ++c) {
                if (c == t0 || c == t1 || c == t2) continue;
                float v = As[c * 65 + c];
                if (v > best) { best = v; bi = c; }
            }
            if (j == 0) t0 = bi; else if (j == 1) t1 = bi; else t2 = bi;
            topi[j] = bi;
        }
    }
    __syncthreads();
    // persist V for warm start, write Ur
    for (int e = tid; e < CHA * CHA; e += NTHREADS)
        g_V[(size_t)b * (CHA * CHA) + e] = Vs[(e >> 6) * 65 + (e & 63)];
    if (tid < CHA * RRANK) {
        int c = tid / RRANK, j = tid % RRANK;
        g_Ur[b * (CHA * RRANK) + tid] = Vs[c * 65 + topi[j]];
    }
}

// ============================================================
// Fused per-iteration pass:
//   stage L tile -> c = Ur^T L (per-pixel) -> UV, losses,
//   L_{t+1} (gmem + smem) -> fused Gram of L_{t+1}
// Final iter: write UV to out, skip L/Gram.
// ============================================================
__global__ __launch_bounds__(NTHREADS) void k_iter(const float* __restrict__ x,
                                                   const float* __restrict__ W,
                                                   float* __restrict__ out,
                                                   int t, int final, int useX)
{
    __shared__ __align__(16) float tile[TP * TSTR];   // 34816 B
    __shared__ float ur[CHA * RRANK];
    __shared__ float pc[3 * NTHREADS];
    __shared__ float red[NTHREADS];

    const int tid = threadIdx.x;
    const int cta = blockIdx.x;
    const int b   = blockIdx.y;
    const int p   = tid & 127;
    const int cg  = tid >> 7;          // channel half: 0 or 1
    const int tr  = (tid >> 4) << 2;
    const int tc  = (tid & 15) << 2;

    if (tid < CHA * RRANK) ur[tid] = g_Ur[b * (CHA * RRANK) + tid];

    const float rho = g_rho0 * powf(1.05f, (float)t);
    const float* __restrict__ Ls = useX ? x : (const float*)g_L;

    unsigned long long acc[8];
    {
        float zz = 0.0f;
#pragma unroll
        for (int i = 0; i < 8; ++i) PACKD(acc[i], zz);
    }
    float lF = 0.0f, lU = 0.0f;

    for (int s = 0; s < SUBT; ++s) {
        const int n = cta * PIX_PER_CTA + s * TP + p;
        const size_t cbase = (((size_t)b * CHA + cg * 32) << 14) + n;

        __syncthreads();   // protect tile from previous subtile's gram readers
        // ---- stage L tile: thread (p, cg) loads channels cg*32..+31 ----
#pragma unroll
        for (int q = 0; q < 8; ++q) {
            const size_t i0 = cbase + ((size_t)(q * 4) << 14);
            float4 v;
            v.x = Ls[i0];
            v.y = Ls[i0 + (size_t)(1 << 14)];
            v.z = Ls[i0 + (size_t)(2 << 14)];
            v.w = Ls[i0 + (size_t)(3 << 14)];
            *(float4*)&tile[p * TSTR + cg * 32 + q * 4] = v;   // STS.128, conflict-free
        }
        __syncthreads();

        // ---- c partials: c(:,n) = Ur^T L(:,n), split across channel halves ----
        float a0 = 0.0f, a1 = 0.0f, a2 = 0.0f;
#pragma unroll
        for (int q = 0; q < 8; ++q) {
            const int c0 = cg * 32 + q * 4;
            float4 lv = *(const float4*)&tile[p * TSTR + c0];
            a0 += ur[(c0  )*3  ] * lv.x; a1 += ur[(c0  )*3+1] * lv.x; a2 += ur[(c0  )*3+2] * lv.x;
            a0 += ur[(c0+1)*3  ] * lv.y; a1 += ur[(c0+1)*3+1] * lv.y; a2 += ur[(c0+1)*3+2] * lv.y;
            a0 += ur[(c0+2)*3  ] * lv.z; a1 += ur[(c0+2)*3+1] * lv.z; a2 += ur[(c0+2)*3+2] * lv.z;
            a0 += ur[(c0+3)*3  ] * lv.w; a1 += ur[(c0+3)*3+1] * lv.w; a2 += ur[(c0+3)*3+2] * lv.w;
        }
        pc[tid] = a0; pc[NTHREADS + tid] = a1; pc[2 * NTHREADS + tid] = a2;
        __syncthreads();
        const float C0 = pc[p] + pc[128 + p];
        const float C1 = pc[NTHREADS + p] + pc[NTHREADS + 128 + p];
        const float C2 = pc[2*NTHREADS + p] + pc[2*NTHREADS + 128 + p];

        // ---- UV, losses, blend, write L_{t+1} (gmem + tile) ----
#pragma unroll
        for (int q = 0; q < 8; ++q) {
            const int c0 = cg * 32 + q * 4;
            const size_t i0 = cbase + ((size_t)(q * 4) << 14);
            float lnv[4];
#pragma unroll
            for (int j = 0; j < 4; ++j) {
                const int cc = c0 + j;
                const size_t idx = i0 + ((size_t)j << 14);
                float uv = ur[cc*3] * C0 + ur[cc*3+1] * C1 + ur[cc*3+2] * C2;
                float xv = x[idx];
                float wv = W[idx];
                float d  = uv - xv;
                lF += wv * d * d;
                lU += uv * uv;
                if (final) {
                    out[idx] = uv;
                } else {
                    float mu = rho / (wv + rho);
                    float ln = (1.0f - mu) * xv + mu * uv;
                    g_L[idx] = ln;
                    lnv[j]   = ln;
                }
            }
            if (!final)
                *(float4*)&tile[p * TSTR + c0] = *(float4*)lnv;
        }

        if (!final) {
            __syncthreads();
            // ---- fused Gram of L_{t+1}: 4x4 block per thread, f32x2 FMA ----
#pragma unroll 2
            for (int pp = 0; pp < TP; ++pp) {
                const float4 av = *(const float4*)&tile[pp * TSTR + tr];
                const float4 bv = *(const float4*)&tile[pp * TSTR + tc];
                unsigned long long b01, b23, q0, q1, q2, q3;
                PACK2(b01, bv.x, bv.y);
                PACK2(b23, bv.z, bv.w);
                PACKD(q0, av.x); PACKD(q1, av.y); PACKD(q2, av.z); PACKD(q3, av.w);
                FMA2(acc[0], q0, b01); FMA2(acc[1], q0, b23);
                FMA2(acc[2], q1, b01); FMA2(acc[3], q1, b23);
                FMA2(acc[4], q2, b01); FMA2(acc[5], q2, b23);
                FMA2(acc[6], q3, b01); FMA2(acc[7], q3, b23);
            }
        }
    }

    if (!final) {
        const size_t gb = ((size_t)(b * PB_CTAS + cta)) * (CHA * CHA);
#pragma unroll
        for (int i = 0; i < 4; ++i) {
            float lo, hi;
            UNPK2(lo, hi, acc[i * 2]);
            g_Gpart[gb + (size_t)(tr + i) * CHA + tc    ] = lo;
            g_Gpart[gb + (size_t)(tr + i) * CHA + tc + 1] = hi;
            UNPK2(lo, hi, acc[i * 2 + 1]);
            g_Gpart[gb + (size_t)(tr + i) * CHA + tc + 2] = lo;
            g_Gpart[gb + (size_t)(tr + i) * CHA + tc + 3] = hi;
        }
    }

    // deterministic loss partials
    __syncthreads();
    red[tid] = lF; __syncthreads();
    for (int st = NTHREADS/2; st > 0; st >>= 1) {
        if (tid < st) red[tid] += red[tid + st];
        __syncthreads();
    }
    if (tid == 0) g_losspart[0][t][b * PB_CTAS + cta] = red[0];
    __syncthreads();
    red[tid] = lU; __syncthreads();
    for (int st = NTHREADS/2; st > 0; st >>= 1) {
        if (tid < st) red[tid] += red[tid + st];
        __syncthreads();
    }
    if (tid == 0) g_losspart[1][t][b * PB_CTAS + cta] = red[0];
}

// ============================================================
// final loss reduction -> out tail
// ============================================================
__global__ __launch_bounds__(NTHREADS) void k_loss_final(float* __restrict__ out)
{
    __shared__ double rd[NTHREADS];
    const int id   = blockIdx.x;       // 0..39
    const int type = id / ITEN;        // 0 = loss_F, 1 = loss
    const int t    = id % ITEN;
    double s = 0.0;
    for (int i = threadIdx.x; i < BANDS * PB_CTAS; i += NTHREADS)
        s += (double)g_losspart[type][t][i];
    rd[threadIdx.x] = s;
    __syncthreads();
    for (int st = NTHREADS/2; st > 0; st >>= 1) {
        if (threadIdx.x < st) rd[threadIdx.x] += rd[threadIdx.x + st];
        __syncthreads();
    }
    if (threadIdx.x == 0)
        out[(size_t)67108864 + (size_t)type * ITEN + t] = (float)(rd[0] / 67108864.0);
}

// ============================================================
extern "C" void kernel_launch(void* const* d_in, const int* in_sizes, int n_in,
                              void* d_out, int out_size)
{
    const float* x = (const float*)d_in[0];
    const float* W = (const float*)d_in[1];
    float* out = (float*)d_out;

    k_wsum1<<<1024, NTHREADS>>>(W);                       // launch 0
    k_wsum2<<<1, NTHREADS>>>();                           // launch 1
    k_initV<<<BANDS, NTHREADS>>>();                       // launch 2
    k_gram0<<<dim3(PB_CTAS, BANDS), NTHREADS>>>(x);       // launch 3

    for (int t = 0; t < ITEN; ++t) {
        k_eigen<<<BANDS, NTHREADS>>>(t);                  // launch 4, 6, ...
        k_iter<<<dim3(PB_CTAS, BANDS), NTHREADS>>>(       // launch 5 (ncu -s 5 lands here)
            x, W, out, t, (t == ITEN - 1) ? 1 : 0, (t == 0) ? 1 : 0);
    }
    k_loss_final<<<40, NTHREADS>>>(out);
}